// round 12
// baseline (speedup 1.0000x reference)
#include <cuda_runtime.h>
#include <math.h>

#define NB 8192      // batch rows
#define ND 1024      // feature dim
#define NG 8         // tile count
#define TOTAL (NB * ND)          // 8,388,608 floats
#define TOTAL4 (TOTAL / 4)       // 2,097,152 float4
#define R1_BLOCKS 2048
#define R1_THREADS 256
#define R1_PER_THR (TOTAL4 / (R1_BLOCKS * R1_THREADS))   // 4
#define ROWS_PB 4                // rows per block in K3

__device__ float g_partials[R1_BLOCKS];
__device__ float g_mean_scale[2];         // [0] = mean, [1] = sigmoid(wp)
__device__ unsigned int g_ticket = 0;     // reset in-kernel each launch

// ---------------------------------------------------------------------------
// K1: 2048-block partial sums. Each thread issues 4 BATCHED independent
// float4 loads (MLP=4, no loop-carried address dep) — tuned for the
// L2-resident case (xf stays in L2 across graph replays thanks to __stcs
// output streaming). LAST block reduces 2048 partials in fixed order.
// ---------------------------------------------------------------------------
__global__ void __launch_bounds__(R1_THREADS) k_mean(
    const float4* __restrict__ x4, const float* __restrict__ wp) {
    __shared__ float smem[R1_THREADS / 32];
    __shared__ bool s_last;
    int tid = threadIdx.x;
    int gid = blockIdx.x * R1_THREADS + tid;
    const int stride = R1_BLOCKS * R1_THREADS;   // 524288

    // 4 independent loads, issued back-to-back
    float4 v[R1_PER_THR];
    #pragma unroll
    for (int i = 0; i < R1_PER_THR; i++)
        v[i] = x4[gid + i * stride];

    float s = 0.0f;
    #pragma unroll
    for (int i = 0; i < R1_PER_THR; i++)
        s += (v[i].x + v[i].y) + (v[i].z + v[i].w);

    #pragma unroll
    for (int off = 16; off > 0; off >>= 1)
        s += __shfl_down_sync(0xFFFFFFFFu, s, off);
    if ((tid & 31) == 0) smem[tid >> 5] = s;
    __syncthreads();
    if (tid == 0) {
        float t = 0.0f;
        #pragma unroll
        for (int w = 0; w < R1_THREADS / 32; w++) t += smem[w];
        g_partials[blockIdx.x] = t;
        __threadfence();
        unsigned int tk = atomicAdd(&g_ticket, 1u);
        s_last = (tk == R1_BLOCKS - 1);
    }
    __syncthreads();

    if (s_last) {
        // 2048 partials: 8 per thread in fixed order, then tree
        float a = 0.0f;
        #pragma unroll
        for (int i = 0; i < R1_BLOCKS / R1_THREADS; i++)
            a += g_partials[tid + i * R1_THREADS];
        #pragma unroll
        for (int off = 16; off > 0; off >>= 1)
            a += __shfl_down_sync(0xFFFFFFFFu, a, off);
        if ((tid & 31) == 0) smem[tid >> 5] = a;
        __syncthreads();
        if (tid == 0) {
            float t = 0.0f;
            #pragma unroll
            for (int w = 0; w < R1_THREADS / 32; w++) t += smem[w];
            g_mean_scale[0] = t * (1.0f / (float)TOTAL);
            g_mean_scale[1] = 1.0f / (1.0f + expf(-wp[0]));
            g_ticket = 0;          // reset for next graph replay
            __threadfence();
        }
    }
}

// ---------------------------------------------------------------------------
// K3 (R4-proven shape, unchanged): 4 rows/block, batched loads, fused
// reduction, 32-deep streaming-store burst per thread.
// ---------------------------------------------------------------------------
__global__ void __launch_bounds__(256) k_row_norm_tile(
    const float4* __restrict__ x4, float4* __restrict__ out4) {
    __shared__ float smem[ROWS_PB][8];
    __shared__ float s_inv[ROWS_PB];
    int tid = threadIdx.x;                       // 0..255 -> one float4 per row
    long long row0 = (long long)blockIdx.x * ROWS_PB;

    float mean  = g_mean_scale[0];
    float scale = g_mean_scale[1];

    float4 v[ROWS_PB];
    #pragma unroll
    for (int r = 0; r < ROWS_PB; r++)
        v[r] = x4[(row0 + r) * (ND / 4) + tid];

    float ss[ROWS_PB];
    #pragma unroll
    for (int r = 0; r < ROWS_PB; r++) {
        v[r].x = fmaxf(v[r].x - mean, 0.0f);
        v[r].y = fmaxf(v[r].y - mean, 0.0f);
        v[r].z = fmaxf(v[r].z - mean, 0.0f);
        v[r].w = fmaxf(v[r].w - mean, 0.0f);
        ss[r] = v[r].x * v[r].x + v[r].y * v[r].y
              + v[r].z * v[r].z + v[r].w * v[r].w;
    }

    #pragma unroll
    for (int off = 16; off > 0; off >>= 1) {
        #pragma unroll
        for (int r = 0; r < ROWS_PB; r++)
            ss[r] += __shfl_down_sync(0xFFFFFFFFu, ss[r], off);
    }
    if ((tid & 31) == 0) {
        #pragma unroll
        for (int r = 0; r < ROWS_PB; r++)
            smem[r][tid >> 5] = ss[r];
    }
    __syncthreads();
    if (tid < ROWS_PB) {
        float t = 0.0f;
        #pragma unroll
        for (int w = 0; w < 8; w++) t += smem[tid][w];
        s_inv[tid] = scale / fmaxf(sqrtf(t), 1e-12f);
    }
    __syncthreads();

    #pragma unroll
    for (int r = 0; r < ROWS_PB; r++) {
        float inv = s_inv[r];
        float4 o;
        o.x = v[r].x * inv; o.y = v[r].y * inv;
        o.z = v[r].z * inv; o.w = v[r].w * inv;
        float4* orow = out4 + (row0 + r) * (NG * ND / 4);
        #pragma unroll
        for (int g = 0; g < NG; g++)
            __stcs(&orow[g * (ND / 4) + tid], o);   // streaming, evict-first
    }
}

// ---------------------------------------------------------------------------
extern "C" void kernel_launch(void* const* d_in, const int* in_sizes, int n_in,
                              void* d_out, int out_size) {
    const float4* xf = (const float4*)d_in[0];   // [8192, 1024] fp32
    const float*  wp = (const float*)d_in[1];    // [1] fp32
    // d_in[2] = W_tile — structurally kron(ones(1,G), eye(D)): unused.
    float4* out = (float4*)d_out;                // [8192, 8192] fp32

    k_mean<<<R1_BLOCKS, R1_THREADS>>>(xf, wp);
    k_row_norm_tile<<<NB / ROWS_PB, 256>>>(xf, out);
}

// round 14
// speedup vs baseline: 1.0686x; 1.0686x over previous
#include <cuda_runtime.h>
#include <math.h>

#define NB 8192      // batch rows
#define ND 1024      // feature dim
#define NG 8         // tile count
#define TOTAL (NB * ND)          // 8,388,608 floats
#define TOTAL4 (TOTAL / 4)       // 2,097,152 float4
#define R1_BLOCKS 1024
#define R1_THREADS 256

__device__ float g_partials[R1_BLOCKS];
__device__ float g_mean_scale[2];         // [0] = mean, [1] = sigmoid(wp)
__device__ unsigned int g_ticket = 0;     // reset in-kernel each launch

// ---------------------------------------------------------------------------
// K1: per-block partial sums of xf; the LAST block to finish reduces all
// 1024 partials in a fixed order (deterministic) and writes mean + sigmoid.
// (R4-proven configuration: 1024 blocks x 256 thr, 8-deep load loop.)
// ---------------------------------------------------------------------------
__global__ void __launch_bounds__(R1_THREADS) k_mean(
    const float4* __restrict__ x4, const float* __restrict__ wp) {
    __shared__ float smem[R1_THREADS / 32];
    __shared__ bool s_last;
    int tid = threadIdx.x;
    int gid = blockIdx.x * R1_THREADS + tid;
    const int stride = R1_BLOCKS * R1_THREADS;   // 262144

    float s = 0.0f;
    #pragma unroll
    for (int i = 0; i < TOTAL4 / stride; i++) {  // 8 iterations, MLP=8
        float4 v = x4[gid + i * stride];
        s += (v.x + v.y) + (v.z + v.w);
    }
    #pragma unroll
    for (int off = 16; off > 0; off >>= 1)
        s += __shfl_down_sync(0xFFFFFFFFu, s, off);
    if ((tid & 31) == 0) smem[tid >> 5] = s;
    __syncthreads();
    if (tid == 0) {
        float t = 0.0f;
        #pragma unroll
        for (int w = 0; w < R1_THREADS / 32; w++) t += smem[w];
        g_partials[blockIdx.x] = t;
        __threadfence();
        unsigned int tk = atomicAdd(&g_ticket, 1u);
        s_last = (tk == R1_BLOCKS - 1);
    }
    __syncthreads();

    if (s_last) {
        float a = 0.0f;
        #pragma unroll
        for (int i = 0; i < R1_BLOCKS / R1_THREADS; i++)
            a += g_partials[tid + i * R1_THREADS];
        #pragma unroll
        for (int off = 16; off > 0; off >>= 1)
            a += __shfl_down_sync(0xFFFFFFFFu, a, off);
        if ((tid & 31) == 0) smem[tid >> 5] = a;
        __syncthreads();
        if (tid == 0) {
            float t = 0.0f;
            #pragma unroll
            for (int w = 0; w < R1_THREADS / 32; w++) t += smem[w];
            g_mean_scale[0] = t * (1.0f / (float)TOTAL);
            g_mean_scale[1] = 1.0f / (1.0f + expf(-wp[0]));
            g_ticket = 0;          // reset for next graph replay
            __threadfence();
        }
    }
}

// ---------------------------------------------------------------------------
// K3 (R4-proven): one block per row. relu(x - mean), row L2 norm, scaled
// write x8 tiles with streaming (evict-first) stores so xf stays L2-resident
// for the next replay's k_mean.
// ---------------------------------------------------------------------------
__global__ void __launch_bounds__(256) k_row_norm_tile(
    const float4* __restrict__ x4, float4* __restrict__ out4) {
    __shared__ float smem[8];
    __shared__ float s_inv;
    int tid = threadIdx.x;           // 0..255 -> one float4 each (D=1024)
    long long row = blockIdx.x;

    float mean  = g_mean_scale[0];
    float scale = g_mean_scale[1];

    float4 v = x4[row * (ND / 4) + tid];
    v.x = fmaxf(v.x - mean, 0.0f);
    v.y = fmaxf(v.y - mean, 0.0f);
    v.z = fmaxf(v.z - mean, 0.0f);
    v.w = fmaxf(v.w - mean, 0.0f);

    float ss = v.x * v.x + v.y * v.y + v.z * v.z + v.w * v.w;
    #pragma unroll
    for (int off = 16; off > 0; off >>= 1)
        ss += __shfl_down_sync(0xFFFFFFFFu, ss, off);
    if ((tid & 31) == 0) smem[tid >> 5] = ss;
    __syncthreads();
    if (tid == 0) {
        float t = 0.0f;
        #pragma unroll
        for (int w = 0; w < 8; w++) t += smem[w];
        float nrm = fmaxf(sqrtf(t), 1e-12f);
        s_inv = scale / nrm;
    }
    __syncthreads();

    float inv = s_inv;
    float4 o;
    o.x = v.x * inv; o.y = v.y * inv; o.z = v.z * inv; o.w = v.w * inv;

    // output row stride = G*D = 8192 floats = 2048 float4
    float4* orow = out4 + row * (NG * ND / 4);
    #pragma unroll
    for (int g = 0; g < NG; g++)
        __stcs(&orow[g * (ND / 4) + tid], o);   // streaming store, evict-first
}

// ---------------------------------------------------------------------------
extern "C" void kernel_launch(void* const* d_in, const int* in_sizes, int n_in,
                              void* d_out, int out_size) {
    const float4* xf = (const float4*)d_in[0];   // [8192, 1024] fp32
    const float*  wp = (const float*)d_in[1];    // [1] fp32
    // d_in[2] = W_tile — structurally kron(ones(1,G), eye(D)): unused.
    float4* out = (float4*)d_out;                // [8192, 8192] fp32

    k_mean<<<R1_BLOCKS, R1_THREADS>>>(xf, wp);
    k_row_norm_tile<<<NB, 256>>>(xf, out);
}